// round 4
// baseline (speedup 1.0000x reference)
#include <cuda_runtime.h>
#include <cuda_bf16.h>
#include <cstdint>

// Problem: B=2, H=16, S=2048, D=128, temperature=1. Output tuple = (O, attn).
constexpr int kS = 2048;
constexpr int kD = 128;
constexpr int kBH = 32;
constexpr int kQT = 128;            // q rows per CTA
constexpr int kKT = 64;             // keys per tile
constexpr int kTiles = kS / kKT;    // 32
constexpr int kThreads = 256;       // 8 warps
constexpr float kScaleLog2e = 0.08838834764831845f * 1.4426950408889634f;

// smem (bytes): Q hi/lo 128x128 bf16; two K/V buffers; rowsum inverses
constexpr int SM_QHI  = 0;
constexpr int SM_QLO  = 32768;
constexpr int SM_BUF0 = 65536;
constexpr int BUF_SZ  = 65536;      // KHI 16K | KLO 16K | VHI 16K | VLO 16K
constexpr int OFF_KHI = 0;
constexpr int OFF_KLO = 16384;
constexpr int OFF_VHI = 32768;
constexpr int OFF_VLO = 49152;
constexpr int SM_RSUM = SM_BUF0 + 2 * BUF_SZ;   // 196608
constexpr int SM_TOTAL = SM_RSUM + 512;         // 197120

__device__ __forceinline__ uint32_t smem_u32(const void* p) {
    uint32_t a;
    asm("{ .reg .u64 t; cvta.to.shared.u64 t, %1; cvt.u32.u64 %0, t; }" : "=r"(a) : "l"(p));
    return a;
}
__device__ __forceinline__ float ex2f(float x) {
    float y; asm("ex2.approx.f32 %0, %1;" : "=f"(y) : "f"(x)); return y;
}

#define LDSM4(r, addr) \
    asm volatile("ldmatrix.sync.aligned.m8n8.x4.shared.b16 {%0,%1,%2,%3}, [%4];" \
        : "=r"((r)[0]), "=r"((r)[1]), "=r"((r)[2]), "=r"((r)[3]) : "r"(addr))

#define MMA(c, a, b0_, b1_) \
    asm volatile("mma.sync.aligned.m16n8k16.row.col.f32.bf16.bf16.f32 " \
        "{%0,%1,%2,%3}, {%4,%5,%6,%7}, {%8,%9}, {%0,%1,%2,%3};" \
        : "+f"((c)[0]), "+f"((c)[1]), "+f"((c)[2]), "+f"((c)[3]) \
        : "r"((a)[0]), "r"((a)[1]), "r"((a)[2]), "r"((a)[3]), "r"(b0_), "r"(b1_))

__device__ __forceinline__ void split2(float a, float b, uint32_t& hi, uint32_t& lo) {
    __nv_bfloat162 h = __floats2bfloat162_rn(a, b);
    hi = reinterpret_cast<const uint32_t&>(h);
    float ra = a - __bfloat162float(__low2bfloat16(h));
    float rb = b - __bfloat162float(__high2bfloat16(h));
    __nv_bfloat162 l = __floats2bfloat162_rn(ra, rb);
    lo = reinterpret_cast<const uint32_t&>(l);
}
__device__ __forceinline__ void split8(const float* v, uint4& hi, uint4& lo) {
    uint32_t h[4], l[4];
    #pragma unroll
    for (int j = 0; j < 4; j++) split2(v[2 * j], v[2 * j + 1], h[j], l[j]);
    hi = make_uint4(h[0], h[1], h[2], h[3]);
    lo = make_uint4(l[0], l[1], l[2], l[3]);
}

// gmem -> regs (raw floats) for one K/V tile
__device__ __forceinline__ void load_k_regs(const float* Kg, int k0, int tid, float* kf) {
    #pragma unroll
    for (int it = 0; it < 4; it++) {
        int idx = it * kThreads + tid;
        int r = idx >> 4, ch = idx & 15;
        const float* kp = Kg + (size_t)(k0 + r) * kD + ch * 8;
        #pragma unroll
        for (int j = 0; j < 8; j++) kf[it * 8 + j] = kp[j];
    }
}
__device__ __forceinline__ void load_v_regs(const float* Vg, int k0, int tid, float* vf) {
    #pragma unroll
    for (int it = 0; it < 4; it++) {
        int i = it * kThreads + tid;
        int d = i & 127, kc8 = i >> 7;
        const float* vp = Vg + (size_t)(k0 + kc8 * 8) * kD + d;
        #pragma unroll
        for (int j = 0; j < 8; j++) vf[it * 8 + j] = vp[(size_t)j * kD];
    }
}
// regs -> swizzled smem buffer (split hi/lo)
__device__ __forceinline__ void store_tile(char* sm8, int bufbase, const float* kf,
                                           const float* vf, int tid) {
    #pragma unroll
    for (int it = 0; it < 4; it++) {
        int idx = it * kThreads + tid;
        int r = idx >> 4, ch = idx & 15;
        uint4 hi, lo; split8(kf + it * 8, hi, lo);
        uint32_t off = (uint32_t)(r * 256 + ((ch ^ (r & 7)) << 4));
        *(uint4*)(sm8 + bufbase + OFF_KHI + off) = hi;
        *(uint4*)(sm8 + bufbase + OFF_KLO + off) = lo;
    }
    #pragma unroll
    for (int it = 0; it < 4; it++) {
        int i = it * kThreads + tid;
        int d = i & 127, kc8 = i >> 7;
        uint4 hi, lo; split8(vf + it * 8, hi, lo);
        uint32_t off = (uint32_t)(d * 128 + ((kc8 ^ (d & 7)) << 4));
        *(uint4*)(sm8 + bufbase + OFF_VHI + off) = hi;
        *(uint4*)(sm8 + bufbase + OFF_VLO + off) = lo;
    }
}

__global__ __launch_bounds__(kThreads, 1)
void sdpa_mma_kernel(const float* __restrict__ Q, const float* __restrict__ K,
                     const float* __restrict__ V, const int* __restrict__ mask,
                     float* __restrict__ outO, float* __restrict__ outA) {
    extern __shared__ char sm8[];
    const uint32_t smb = smem_u32(sm8);
    const int tid = threadIdx.x;
    const int wid = tid >> 5, lane = tid & 31;
    const int bh = blockIdx.y;
    const int q0 = blockIdx.x * kQT;
    const int r0 = wid * 16;
    const int g  = lane >> 2;
    const int qt = lane & 3;
    const int lrow = lane & 15, lsel = lane >> 4;

    const float* Qg = Q + ((size_t)bh * kS + q0) * kD;
    const float* Kg = K + (size_t)bh * kS * kD;
    const float* Vg = V + (size_t)bh * kS * kD;

    // ---- Q load (prescaled), split hi/lo into smem ----
    #pragma unroll
    for (int it = 0; it < 8; it++) {
        int idx = it * kThreads + tid;
        int r = idx >> 4, ch = idx & 15;
        const float* qp = Qg + (size_t)r * kD + ch * 8;
        float v[8];
        #pragma unroll
        for (int j = 0; j < 8; j++) v[j] = qp[j] * kScaleLog2e;
        uint4 hi, lo; split8(v, hi, lo);
        uint32_t off = (uint32_t)(r * 256 + ((ch ^ (r & 7)) << 4));
        *(uint4*)(sm8 + SM_QHI + off) = hi;
        *(uint4*)(sm8 + SM_QLO + off) = lo;
    }

    // ---- preload tile 0 into buffer 0 ----
    {
        float kf[32], vf[32];
        load_k_regs(Kg, 0, tid, kf);
        load_v_regs(Vg, 0, tid, vf);
        store_tile(sm8, SM_BUF0, kf, vf, tid);
    }

    float oacc[16][4];
    #pragma unroll
    for (int i = 0; i < 16; i++)
        #pragma unroll
        for (int j = 0; j < 4; j++) oacc[i][j] = 0.0f;
    float sum0 = 0.0f, sum1 = 0.0f;

    for (int kt = 0; kt < kTiles; kt++) {
        const int k0 = kt * kKT;
        const int curbase = SM_BUF0 + (kt & 1) * BUF_SZ;
        const bool pre = (kt + 1 < kTiles);
        float kf[32], vf[32];

        __syncthreads();   // back-buffer stores (prev iter) complete

        // prefetch next K early: 8 LDG.128/warp, completes during S phase
        if (pre) load_k_regs(Kg, k0 + kKT, tid, kf);

        // ---- S = Q @ K^T  (16x64 per warp, 3-term bf16) ----
        float sacc[8][4];
        #pragma unroll
        for (int i = 0; i < 8; i++)
            #pragma unroll
            for (int j = 0; j < 4; j++) sacc[i][j] = 0.0f;

        #pragma unroll
        for (int c = 0; c < 8; c++) {
            uint32_t ah[4], al[4];
            {
                int ar = r0 + lrow;
                int ac = 2 * c + lsel;
                uint32_t qa = smb + SM_QHI + (uint32_t)(ar * 256 + ((ac ^ (ar & 7)) << 4));
                LDSM4(ah, qa);
                LDSM4(al, qa + (SM_QLO - SM_QHI));
            }
            #pragma unroll
            for (int np = 0; np < 4; np++) {
                int br = np * 16 + lrow;
                int bc = 2 * c + lsel;
                uint32_t kb = smb + curbase + OFF_KHI + (uint32_t)(br * 256 + ((bc ^ (br & 7)) << 4));
                uint32_t bhf[4], blf[4];
                LDSM4(bhf, kb);
                LDSM4(blf, kb + (OFF_KLO - OFF_KHI));
                MMA(sacc[2 * np],     ah, bhf[0], bhf[2]);
                MMA(sacc[2 * np + 1], ah, bhf[1], bhf[3]);
                MMA(sacc[2 * np],     ah, blf[0], blf[2]);
                MMA(sacc[2 * np + 1], ah, blf[1], blf[3]);
                MMA(sacc[2 * np],     al, bhf[0], bhf[2]);
                MMA(sacc[2 * np + 1], al, bhf[1], bhf[3]);
            }
        }

        // ---- epilogue: mask + ex2, write unnormalized attn, keep P in regs ----
        {
            const int row_lo = q0 + r0 + g, row_hi = row_lo + 8;
            const int* m_lo = mask + (size_t)row_lo * kS + k0 + qt * 2;
            const int* m_hi = mask + (size_t)row_hi * kS + k0 + qt * 2;
            float* a_lo = outA + ((size_t)bh * kS + row_lo) * kS + k0 + qt * 2;
            float* a_hi = outA + ((size_t)bh * kS + row_hi) * kS + k0 + qt * 2;
            #pragma unroll
            for (int nt = 0; nt < 8; nt++) {
                int2 m0 = *(const int2*)(m_lo + nt * 8);
                int2 m1 = *(const int2*)(m_hi + nt * 8);
                float p0 = m0.x ? ex2f(sacc[nt][0]) : 0.0f;
                float p1 = m0.y ? ex2f(sacc[nt][1]) : 0.0f;
                float p2 = m1.x ? ex2f(sacc[nt][2]) : 0.0f;
                float p3 = m1.y ? ex2f(sacc[nt][3]) : 0.0f;
                sum0 += p0 + p1;
                sum1 += p2 + p3;
                *(float2*)(a_lo + nt * 8) = make_float2(p0, p1);
                *(float2*)(a_hi + nt * 8) = make_float2(p2, p3);
                sacc[nt][0] = p0; sacc[nt][1] = p1; sacc[nt][2] = p2; sacc[nt][3] = p3;
            }
        }

        // prefetch next V: 32 LDG.32/warp, completes during PV phase
        if (pre) load_v_regs(Vg, k0 + kKT, tid, vf);

        // ---- O += P @ Vt^T (P from registers; 3-term) ----
        #pragma unroll
        for (int kc = 0; kc < 4; kc++) {
            uint32_t ahiF[4], aloF[4];
            split2(sacc[2 * kc][0],     sacc[2 * kc][1],     ahiF[0], aloF[0]);
            split2(sacc[2 * kc][2],     sacc[2 * kc][3],     ahiF[1], aloF[1]);
            split2(sacc[2 * kc + 1][0], sacc[2 * kc + 1][1], ahiF[2], aloF[2]);
            split2(sacc[2 * kc + 1][2], sacc[2 * kc + 1][3], ahiF[3], aloF[3]);
            #pragma unroll
            for (int np = 0; np < 8; np++) {
                int br = np * 16 + lrow;
                int bc = 2 * kc + lsel;
                uint32_t vb = smb + curbase + OFF_VHI + (uint32_t)(br * 128 + ((bc ^ (br & 7)) << 4));
                uint32_t bhf[4], blf[4];
                LDSM4(bhf, vb);
                LDSM4(blf, vb + (OFF_VLO - OFF_VHI));
                MMA(oacc[2 * np],     ahiF, bhf[0], bhf[2]);
                MMA(oacc[2 * np + 1], ahiF, bhf[1], bhf[3]);
                MMA(oacc[2 * np],     ahiF, blf[0], blf[2]);
                MMA(oacc[2 * np + 1], ahiF, blf[1], blf[3]);
                MMA(oacc[2 * np],     aloF, bhf[0], bhf[2]);
                MMA(oacc[2 * np + 1], aloF, bhf[1], bhf[3]);
            }
        }

        // store prefetched tile into back buffer (visible after next sync)
        if (pre) store_tile(sm8, SM_BUF0 + ((kt + 1) & 1) * BUF_SZ, kf, vf, tid);
    }

    // ---- finalize: reduce rowsums across quad, write O, stash inverses ----
    sum0 += __shfl_xor_sync(0xffffffffu, sum0, 1);
    sum0 += __shfl_xor_sync(0xffffffffu, sum0, 2);
    sum1 += __shfl_xor_sync(0xffffffffu, sum1, 1);
    sum1 += __shfl_xor_sync(0xffffffffu, sum1, 2);
    const int row_lo = q0 + r0 + g, row_hi = row_lo + 8;
    float inv0 = 1.0f / sum0, inv1 = 1.0f / sum1;
    if (qt == 0) {
        ((float*)(sm8 + SM_RSUM))[r0 + g]     = inv0;
        ((float*)(sm8 + SM_RSUM))[r0 + g + 8] = inv1;
    }
    float* o_lo = outO + ((size_t)bh * kS + row_lo) * kD + qt * 2;
    float* o_hi = outO + ((size_t)bh * kS + row_hi) * kD + qt * 2;
    #pragma unroll
    for (int nt = 0; nt < 16; nt++) {
        *(float2*)(o_lo + nt * 8) = make_float2(oacc[nt][0] * inv0, oacc[nt][1] * inv0);
        *(float2*)(o_hi + nt * 8) = make_float2(oacc[nt][2] * inv1, oacc[nt][3] * inv1);
    }

    // ---- tail: normalize this CTA's attn slab (replaces fixup kernel) ----
    __syncthreads();
    const float* invs = (const float*)(sm8 + SM_RSUM);
    float* abase = outA + ((size_t)bh * kS + q0) * kS;
    #pragma unroll 4
    for (int i = 0; i < 256; i++) {
        int idx = i * kThreads + tid;
        int r = idx >> 9, c = idx & 511;
        float inv = invs[r];
        float4* p = (float4*)(abase + (size_t)r * kS) + c;
        float4 v = *p;
        v.x *= inv; v.y *= inv; v.z *= inv; v.w *= inv;
        *p = v;
    }
}

extern "C" void kernel_launch(void* const* d_in, const int* in_sizes, int n_in,
                              void* d_out, int out_size) {
    const float* Q    = (const float*)d_in[0];
    const float* K    = (const float*)d_in[1];
    const float* V    = (const float*)d_in[2];
    const int*   mask = (const int*)d_in[3];

    float* outO = (float*)d_out;
    float* outA = outO + (size_t)kBH * kS * kD;   // tuple order: (output, attn)

    cudaFuncSetAttribute(sdpa_mma_kernel, cudaFuncAttributeMaxDynamicSharedMemorySize, SM_TOTAL);

    dim3 grid(kS / kQT, kBH);
    sdpa_mma_kernel<<<grid, kThreads, SM_TOTAL>>>(Q, K, V, mask, outO, outA);
}

// round 5
// speedup vs baseline: 1.4623x; 1.4623x over previous
#include <cuda_runtime.h>
#include <cuda_bf16.h>
#include <cstdint>

// Problem: B=2, H=16, S=2048, D=128, temperature=1. Output tuple = (O, attn).
constexpr int kS = 2048;
constexpr int kD = 128;
constexpr int kBH = 32;
constexpr int kQT = 128;            // q rows per CTA
constexpr int kKT = 64;             // keys per tile
constexpr int kTiles = kS / kKT;    // 32
constexpr int kThreads = 256;       // 8 warps
constexpr float kScaleLog2e = 0.08838834764831845f * 1.4426950408889634f;

// smem layout (bytes)
constexpr int SM_QHI   = 0;        // 128x128 bf16
constexpr int SM_QLO   = 32768;
constexpr int SM_KHI   = 65536;    // 64x128 bf16 split
constexpr int SM_KLO   = 81920;
constexpr int SM_VHI   = 98304;    // 128(d)x64(key) bf16 split, transposed
constexpr int SM_VLO   = 114688;
constexpr int SM_KSTAG = 131072;   // 64x128 fp32 raw staging (cp.async)
constexpr int SM_VSTAG = 163840;   // 64x128 fp32 raw staging
constexpr int SM_RSUM  = 196608;
constexpr int SM_TOTAL = 197120;

__device__ __forceinline__ uint32_t smem_u32(const void* p) {
    uint32_t a;
    asm("{ .reg .u64 t; cvta.to.shared.u64 t, %1; cvt.u32.u64 %0, t; }" : "=r"(a) : "l"(p));
    return a;
}
__device__ __forceinline__ float ex2f(float x) {
    float y; asm("ex2.approx.f32 %0, %1;" : "=f"(y) : "f"(x)); return y;
}

#define CP_ASYNC16(dst, src) \
    asm volatile("cp.async.cg.shared.global [%0], [%1], 16;" :: "r"(dst), "l"(src))
#define CP_COMMIT()  asm volatile("cp.async.commit_group;")
#define CP_WAIT0()   asm volatile("cp.async.wait_group 0;" ::: "memory")

#define LDSM4(r, addr) \
    asm volatile("ldmatrix.sync.aligned.m8n8.x4.shared.b16 {%0,%1,%2,%3}, [%4];" \
        : "=r"((r)[0]), "=r"((r)[1]), "=r"((r)[2]), "=r"((r)[3]) : "r"(addr))

#define MMA(c, a, b0_, b1_) \
    asm volatile("mma.sync.aligned.m16n8k16.row.col.f32.bf16.bf16.f32 " \
        "{%0,%1,%2,%3}, {%4,%5,%6,%7}, {%8,%9}, {%0,%1,%2,%3};" \
        : "+f"((c)[0]), "+f"((c)[1]), "+f"((c)[2]), "+f"((c)[3]) \
        : "r"((a)[0]), "r"((a)[1]), "r"((a)[2]), "r"((a)[3]), "r"(b0_), "r"(b1_))

__device__ __forceinline__ void split2(float a, float b, uint32_t& hi, uint32_t& lo) {
    __nv_bfloat162 h = __floats2bfloat162_rn(a, b);
    hi = reinterpret_cast<const uint32_t&>(h);
    float ra = a - __bfloat162float(__low2bfloat16(h));
    float rb = b - __bfloat162float(__high2bfloat16(h));
    __nv_bfloat162 l = __floats2bfloat162_rn(ra, rb);
    lo = reinterpret_cast<const uint32_t&>(l);
}
__device__ __forceinline__ void split8(const float* v, uint4& hi, uint4& lo) {
    uint32_t h[4], l[4];
    #pragma unroll
    for (int j = 0; j < 4; j++) split2(v[2 * j], v[2 * j + 1], h[j], l[j]);
    hi = make_uint4(h[0], h[1], h[2], h[3]);
    lo = make_uint4(l[0], l[1], l[2], l[3]);
}

// issue cp.async for K/V tile at key offset k0 into staging (16 x 16B per thread)
__device__ __forceinline__ void cp_tile(uint32_t smb, const float* Kg, const float* Vg,
                                        int k0, int tid) {
    #pragma unroll
    for (int j = 0; j < 8; j++) {
        int idx = j * kThreads + tid;
        int row = idx >> 5, c = idx & 31;                 // row 0..63, 16B chunk 0..31
        const float* srcK = Kg + (size_t)(k0 + row) * kD + c * 4;
        const float* srcV = Vg + (size_t)(k0 + row) * kD + c * 4;
        uint32_t dstK = smb + SM_KSTAG + row * 512 + ((c ^ (row & 7)) << 4);
        uint32_t dstV = smb + SM_VSTAG + row * 512 + c * 16;
        CP_ASYNC16(dstK, srcK);
        CP_ASYNC16(dstV, srcV);
    }
    CP_COMMIT();
}

__global__ __launch_bounds__(kThreads, 1)
void sdpa_mma_kernel(const float* __restrict__ Q, const float* __restrict__ K,
                     const float* __restrict__ V, const int* __restrict__ mask,
                     float* __restrict__ outO, float* __restrict__ outA) {
    extern __shared__ char sm8[];
    const uint32_t smb = smem_u32(sm8);
    const int tid = threadIdx.x;
    const int wid = tid >> 5, lane = tid & 31;
    const int bh = blockIdx.y;
    const int q0 = blockIdx.x * kQT;
    const int r0 = wid * 16;
    const int g  = lane >> 2;
    const int qt = lane & 3;
    const int lrow = lane & 15, lsel = lane >> 4;

    const float* Qg = Q + ((size_t)bh * kS + q0) * kD;
    const float* Kg = K + (size_t)bh * kS * kD;
    const float* Vg = V + (size_t)bh * kS * kD;

    // ---- prologue: start tile-0 staging, then load/split Q ----
    cp_tile(smb, Kg, Vg, 0, tid);

    #pragma unroll
    for (int it = 0; it < 8; it++) {
        int idx = it * kThreads + tid;
        int r = idx >> 4, ch = idx & 15;
        const float* qp = Qg + (size_t)r * kD + ch * 8;
        float v[8];
        #pragma unroll
        for (int j = 0; j < 8; j++) v[j] = qp[j] * kScaleLog2e;
        uint4 hi, lo; split8(v, hi, lo);
        uint32_t off = (uint32_t)(r * 256 + ((ch ^ (r & 7)) << 4));
        *(uint4*)(sm8 + SM_QHI + off) = hi;
        *(uint4*)(sm8 + SM_QLO + off) = lo;
    }

    float oacc[16][4];
    #pragma unroll
    for (int i = 0; i < 16; i++)
        #pragma unroll
        for (int j = 0; j < 4; j++) oacc[i][j] = 0.0f;
    float sum0 = 0.0f, sum1 = 0.0f;

    for (int kt = 0; kt < kTiles; kt++) {
        const int k0 = kt * kKT;

        CP_WAIT0();
        __syncthreads();   // staging ready; split buffers free (prev compute done)

        // ---- convert K: staging raw fp32 -> split bf16 hi/lo (round-3 layout) ----
        {
            const int r = tid & 63, cg = tid >> 2 >> 4;    // cg = tid>>6
            float kv[32];
            #pragma unroll
            for (int j = 0; j < 8; j++) {
                uint32_t a = (uint32_t)(r * 512 + ((((tid >> 6) * 8 + j) ^ (r & 7)) << 4));
                float4 t4 = *(const float4*)(sm8 + SM_KSTAG + a);
                kv[4 * j + 0] = t4.x; kv[4 * j + 1] = t4.y;
                kv[4 * j + 2] = t4.z; kv[4 * j + 3] = t4.w;
            }
            (void)cg;
            #pragma unroll
            for (int q = 0; q < 4; q++) {
                uint4 hi, lo; split8(kv + 8 * q, hi, lo);
                int chunk = (tid >> 6) * 4 + q;
                uint32_t off = (uint32_t)(r * 256 + ((chunk ^ (r & 7)) << 4));
                *(uint4*)(sm8 + SM_KHI + off) = hi;
                *(uint4*)(sm8 + SM_KLO + off) = lo;
            }
        }
        // ---- convert V with transpose: staging [key][d] -> Vt split [d][key] ----
        {
            float vv[32];    // vv[m*8+j] = V[8*wid + j][lane + 32*m]
            #pragma unroll
            for (int m = 0; m < 4; m++)
                #pragma unroll
                for (int j = 0; j < 8; j++)
                    vv[m * 8 + j] = *(const float*)(sm8 + SM_VSTAG +
                        (8 * wid + j) * 512 + (lane + 32 * m) * 4);
            #pragma unroll
            for (int m = 0; m < 4; m++) {
                int d = lane + 32 * m;
                uint32_t h[4], l[4];
                #pragma unroll
                for (int p = 0; p < 4; p++)
                    split2(vv[m * 8 + 2 * p], vv[m * 8 + 2 * p + 1], h[p], l[p]);
                uint32_t off = (uint32_t)(d * 128 + ((wid ^ (d & 7)) << 4));
                *(uint4*)(sm8 + SM_VHI + off) = make_uint4(h[0], h[1], h[2], h[3]);
                *(uint4*)(sm8 + SM_VLO + off) = make_uint4(l[0], l[1], l[2], l[3]);
            }
        }
        __syncthreads();   // split ready; staging free

        // ---- prefetch next tile into staging (overlaps compute) ----
        if (kt + 1 < kTiles) cp_tile(smb, Kg, Vg, k0 + kKT, tid);

        // ---- S = Q @ K^T  (16x64 per warp, 3-term bf16) ----
        float sacc[8][4];
        #pragma unroll
        for (int i = 0; i < 8; i++)
            #pragma unroll
            for (int j = 0; j < 4; j++) sacc[i][j] = 0.0f;

        #pragma unroll
        for (int c = 0; c < 8; c++) {
            uint32_t ah[4], al[4];
            {
                int ar = r0 + lrow;
                int ac = 2 * c + lsel;
                uint32_t qa = smb + SM_QHI + (uint32_t)(ar * 256 + ((ac ^ (ar & 7)) << 4));
                LDSM4(ah, qa);
                LDSM4(al, qa + (SM_QLO - SM_QHI));
            }
            #pragma unroll
            for (int np = 0; np < 4; np++) {
                int br = np * 16 + lrow;
                int bc = 2 * c + lsel;
                uint32_t kb = smb + SM_KHI + (uint32_t)(br * 256 + ((bc ^ (br & 7)) << 4));
                uint32_t bhf[4], blf[4];
                LDSM4(bhf, kb);
                LDSM4(blf, kb + (SM_KLO - SM_KHI));
                MMA(sacc[2 * np],     ah, bhf[0], bhf[2]);
                MMA(sacc[2 * np + 1], ah, bhf[1], bhf[3]);
                MMA(sacc[2 * np],     ah, blf[0], blf[2]);
                MMA(sacc[2 * np + 1], ah, blf[1], blf[3]);
                MMA(sacc[2 * np],     al, bhf[0], bhf[2]);
                MMA(sacc[2 * np + 1], al, bhf[1], bhf[3]);
            }
        }

        // ---- epilogue: mask + ex2, write unnormalized attn, keep P in regs ----
        {
            const int row_lo = q0 + r0 + g, row_hi = row_lo + 8;
            const int* m_lo = mask + (size_t)row_lo * kS + k0 + qt * 2;
            const int* m_hi = mask + (size_t)row_hi * kS + k0 + qt * 2;
            float* a_lo = outA + ((size_t)bh * kS + row_lo) * kS + k0 + qt * 2;
            float* a_hi = outA + ((size_t)bh * kS + row_hi) * kS + k0 + qt * 2;
            #pragma unroll
            for (int nt = 0; nt < 8; nt++) {
                int2 m0 = *(const int2*)(m_lo + nt * 8);
                int2 m1 = *(const int2*)(m_hi + nt * 8);
                float p0 = m0.x ? ex2f(sacc[nt][0]) : 0.0f;
                float p1 = m0.y ? ex2f(sacc[nt][1]) : 0.0f;
                float p2 = m1.x ? ex2f(sacc[nt][2]) : 0.0f;
                float p3 = m1.y ? ex2f(sacc[nt][3]) : 0.0f;
                sum0 += p0 + p1;
                sum1 += p2 + p3;
                *(float2*)(a_lo + nt * 8) = make_float2(p0, p1);
                *(float2*)(a_hi + nt * 8) = make_float2(p2, p3);
                sacc[nt][0] = p0; sacc[nt][1] = p1; sacc[nt][2] = p2; sacc[nt][3] = p3;
            }
        }

        // ---- O += P @ Vt^T (P from registers; 3-term) ----
        #pragma unroll
        for (int kc = 0; kc < 4; kc++) {
            uint32_t ahiF[4], aloF[4];
            split2(sacc[2 * kc][0],     sacc[2 * kc][1],     ahiF[0], aloF[0]);
            split2(sacc[2 * kc][2],     sacc[2 * kc][3],     ahiF[1], aloF[1]);
            split2(sacc[2 * kc + 1][0], sacc[2 * kc + 1][1], ahiF[2], aloF[2]);
            split2(sacc[2 * kc + 1][2], sacc[2 * kc + 1][3], ahiF[3], aloF[3]);
            #pragma unroll
            for (int np = 0; np < 8; np++) {
                int br = np * 16 + lrow;
                int bc = 2 * kc + lsel;
                uint32_t vb = smb + SM_VHI + (uint32_t)(br * 128 + ((bc ^ (br & 7)) << 4));
                uint32_t bhf[4], blf[4];
                LDSM4(bhf, vb);
                LDSM4(blf, vb + (SM_VLO - SM_VHI));
                MMA(oacc[2 * np],     ahiF, bhf[0], bhf[2]);
                MMA(oacc[2 * np + 1], ahiF, bhf[1], bhf[3]);
                MMA(oacc[2 * np],     ahiF, blf[0], blf[2]);
                MMA(oacc[2 * np + 1], ahiF, blf[1], blf[3]);
                MMA(oacc[2 * np],     aloF, bhf[0], bhf[2]);
                MMA(oacc[2 * np + 1], aloF, bhf[1], bhf[3]);
            }
        }
    }

    // ---- finalize: reduce rowsums across quad, write O, stash inverses ----
    sum0 += __shfl_xor_sync(0xffffffffu, sum0, 1);
    sum0 += __shfl_xor_sync(0xffffffffu, sum0, 2);
    sum1 += __shfl_xor_sync(0xffffffffu, sum1, 1);
    sum1 += __shfl_xor_sync(0xffffffffu, sum1, 2);
    const int row_lo = q0 + r0 + g, row_hi = row_lo + 8;
    float inv0 = 1.0f / sum0, inv1 = 1.0f / sum1;
    if (qt == 0) {
        ((float*)(sm8 + SM_RSUM))[r0 + g]     = inv0;
        ((float*)(sm8 + SM_RSUM))[r0 + g + 8] = inv1;
    }
    float* o_lo = outO + ((size_t)bh * kS + row_lo) * kD + qt * 2;
    float* o_hi = outO + ((size_t)bh * kS + row_hi) * kD + qt * 2;
    #pragma unroll
    for (int nt = 0; nt < 16; nt++) {
        *(float2*)(o_lo + nt * 8) = make_float2(oacc[nt][0] * inv0, oacc[nt][1] * inv0);
        *(float2*)(o_hi + nt * 8) = make_float2(oacc[nt][2] * inv1, oacc[nt][3] * inv1);
    }

    // ---- tail: normalize this CTA's attn slab (replaces fixup kernel) ----
    __syncthreads();
    const float* invs = (const float*)(sm8 + SM_RSUM);
    float* abase = outA + ((size_t)bh * kS + q0) * kS;
    #pragma unroll 4
    for (int i = 0; i < 256; i++) {
        int idx = i * kThreads + tid;
        int r = idx >> 9, c = idx & 511;
        float inv = invs[r];
        float4* p = (float4*)(abase + (size_t)r * kS) + c;
        float4 v = *p;
        v.x *= inv; v.y *= inv; v.z *= inv; v.w *= inv;
        *p = v;
    }
}

extern "C" void kernel_launch(void* const* d_in, const int* in_sizes, int n_in,
                              void* d_out, int out_size) {
    const float* Q    = (const float*)d_in[0];
    const float* K    = (const float*)d_in[1];
    const float* V    = (const float*)d_in[2];
    const int*   mask = (const int*)d_in[3];

    float* outO = (float*)d_out;
    float* outA = outO + (size_t)kBH * kS * kD;   // tuple order: (output, attn)

    cudaFuncSetAttribute(sdpa_mma_kernel, cudaFuncAttributeMaxDynamicSharedMemorySize, SM_TOTAL);

    dim3 grid(kS / kQT, kBH);
    sdpa_mma_kernel<<<grid, kThreads, SM_TOTAL>>>(Q, K, V, mask, outO, outA);
}

// round 6
// speedup vs baseline: 1.4630x; 1.0005x over previous
#include <cuda_runtime.h>
#include <cuda_bf16.h>
#include <cstdint>

// Problem: B=2, H=16, S=2048, D=128, temperature=1. Output tuple = (O, attn).
constexpr int kS = 2048;
constexpr int kD = 128;
constexpr int kBH = 32;
constexpr int kQT = 64;             // q rows per CTA
constexpr int kKT = 64;             // keys per tile
constexpr int kTiles = kS / kKT;    // 32
constexpr int kThreads = 256;       // 8 warps: (row-group 0..3) x (half 0..1)
constexpr float kScaleLog2e = 0.08838834764831845f * 1.4426950408889634f;

// smem layout (bytes) — total 114688 = 112KB -> 2 CTAs/SM
constexpr int SM_QHI = 0;          // 64x128 bf16 (256B/row, 16 chunks, swz ch^(r&7))
constexpr int SM_QLO = 16384;
constexpr int SM_KHI = 32768;      // 64x128 bf16 (keys x d)
constexpr int SM_KLO = 49152;
constexpr int SM_VHI = 65536;      // 128(d) x 64(key) bf16 (128B/row, 8 chunks)
constexpr int SM_VLO = 81920;
constexpr int SM_PHI = 98304;      // 64x64 bf16 (128B/row, 8 chunks)
constexpr int SM_PLO = 106496;
constexpr int SM_TOTAL = 114688;
// aliases used only after the main loop (P is dead then):
constexpr int SM_RSUM = SM_PHI;    // 128 floats: [half][row]
constexpr int SM_INV  = SM_PLO;    // 64 floats

__device__ __forceinline__ uint32_t smem_u32(const void* p) {
    uint32_t a;
    asm("{ .reg .u64 t; cvta.to.shared.u64 t, %1; cvt.u32.u64 %0, t; }" : "=r"(a) : "l"(p));
    return a;
}
__device__ __forceinline__ float ex2f(float x) {
    float y; asm("ex2.approx.f32 %0, %1;" : "=f"(y) : "f"(x)); return y;
}

#define LDSM4(r, addr) \
    asm volatile("ldmatrix.sync.aligned.m8n8.x4.shared.b16 {%0,%1,%2,%3}, [%4];" \
        : "=r"((r)[0]), "=r"((r)[1]), "=r"((r)[2]), "=r"((r)[3]) : "r"(addr))

#define MMA(c, a, b0_, b1_) \
    asm volatile("mma.sync.aligned.m16n8k16.row.col.f32.bf16.bf16.f32 " \
        "{%0,%1,%2,%3}, {%4,%5,%6,%7}, {%8,%9}, {%0,%1,%2,%3};" \
        : "+f"((c)[0]), "+f"((c)[1]), "+f"((c)[2]), "+f"((c)[3]) \
        : "r"((a)[0]), "r"((a)[1]), "r"((a)[2]), "r"((a)[3]), "r"(b0_), "r"(b1_))

__device__ __forceinline__ void split2(float a, float b, uint32_t& hi, uint32_t& lo) {
    __nv_bfloat162 h = __floats2bfloat162_rn(a, b);
    hi = reinterpret_cast<const uint32_t&>(h);
    float ra = a - __bfloat162float(__low2bfloat16(h));
    float rb = b - __bfloat162float(__high2bfloat16(h));
    __nv_bfloat162 l = __floats2bfloat162_rn(ra, rb);
    lo = reinterpret_cast<const uint32_t&>(l);
}
__device__ __forceinline__ void split8(const float* v, uint4& hi, uint4& lo) {
    uint32_t h[4], l[4];
    #pragma unroll
    for (int j = 0; j < 4; j++) split2(v[2 * j], v[2 * j + 1], h[j], l[j]);
    hi = make_uint4(h[0], h[1], h[2], h[3]);
    lo = make_uint4(l[0], l[1], l[2], l[3]);
}

__global__ __launch_bounds__(kThreads, 2)
void sdpa_mma_kernel(const float* __restrict__ Q, const float* __restrict__ K,
                     const float* __restrict__ V, const int* __restrict__ mask,
                     float* __restrict__ outO, float* __restrict__ outA) {
    extern __shared__ char sm8[];
    const uint32_t smb = smem_u32(sm8);
    const int tid = threadIdx.x;
    const int wid = tid >> 5, lane = tid & 31;
    const int bh = blockIdx.y;
    const int q0 = blockIdx.x * kQT;
    const int rw = wid & 3, h = wid >> 2;   // row-group / half
    const int r0 = rw * 16;                 // warp's q rows [r0, r0+16)
    const int kh = h * 32;                  // warp's key half (S phase)
    const int g  = lane >> 2;
    const int qt = lane & 3;
    const int lrow = lane & 15, lsel = lane >> 4;

    const float* Qg = Q + ((size_t)bh * kS + q0) * kD;
    const float* Kg = K + (size_t)bh * kS * kD;
    const float* Vg = V + (size_t)bh * kS * kD;

    // ---- prologue: load/split Q (prescaled) ----
    #pragma unroll
    for (int it = 0; it < 4; it++) {
        int idx = it * kThreads + tid;
        int r = idx >> 4, ch = idx & 15;
        const float* qp = Qg + (size_t)r * kD + ch * 8;
        float v[8];
        #pragma unroll
        for (int j = 0; j < 8; j++) v[j] = qp[j] * kScaleLog2e;
        uint4 hi, lo; split8(v, hi, lo);
        uint32_t off = (uint32_t)(r * 256 + ((ch ^ (r & 7)) << 4));
        *(uint4*)(sm8 + SM_QHI + off) = hi;
        *(uint4*)(sm8 + SM_QLO + off) = lo;
    }

    float oacc[8][4];
    #pragma unroll
    for (int i = 0; i < 8; i++)
        #pragma unroll
        for (int j = 0; j < 4; j++) oacc[i][j] = 0.0f;
    float sum0 = 0.0f, sum1 = 0.0f;

    for (int kt = 0; kt < kTiles; kt++) {
        const int k0 = kt * kKT;

        __syncthreads();   // prev tile's S/PV reads of K/V/P done

        // ---- K tile 64(key)x128(d) -> split smem ----
        #pragma unroll
        for (int it = 0; it < 4; it++) {
            int idx = it * kThreads + tid;
            int r = idx >> 4, ch = idx & 15;
            const float* kp = Kg + (size_t)(k0 + r) * kD + ch * 8;
            float v[8];
            #pragma unroll
            for (int j = 0; j < 8; j++) v[j] = kp[j];
            uint4 hi, lo; split8(v, hi, lo);
            uint32_t off = (uint32_t)(r * 256 + ((ch ^ (r & 7)) << 4));
            *(uint4*)(sm8 + SM_KHI + off) = hi;
            *(uint4*)(sm8 + SM_KLO + off) = lo;
        }
        // ---- V tile transposed -> Vt[d][key] split smem ----
        #pragma unroll
        for (int it = 0; it < 4; it++) {
            int i = it * kThreads + tid;
            int d = i & 127, kc8 = i >> 7;   // kc8 in 0..7
            const float* vp = Vg + (size_t)(k0 + kc8 * 8) * kD + d;
            float v[8];
            #pragma unroll
            for (int j = 0; j < 8; j++) v[j] = vp[(size_t)j * kD];
            uint4 hi, lo; split8(v, hi, lo);
            uint32_t off = (uint32_t)(d * 128 + ((kc8 ^ (d & 7)) << 4));
            *(uint4*)(sm8 + SM_VHI + off) = hi;
            *(uint4*)(sm8 + SM_VLO + off) = lo;
        }
        __syncthreads();

        // ---- S = Q @ K^T : warp computes 16q x 32keys (its key half) ----
        float sacc[4][4];
        #pragma unroll
        for (int i = 0; i < 4; i++)
            #pragma unroll
            for (int j = 0; j < 4; j++) sacc[i][j] = 0.0f;

        #pragma unroll
        for (int c = 0; c < 8; c++) {
            uint32_t ah[4], al[4];
            {
                int ar = r0 + lrow;
                int ac = 2 * c + lsel;
                uint32_t qa = smb + SM_QHI + (uint32_t)(ar * 256 + ((ac ^ (ar & 7)) << 4));
                LDSM4(ah, qa);
                LDSM4(al, qa + (SM_QLO - SM_QHI));
            }
            #pragma unroll
            for (int np = 0; np < 2; np++) {
                int br = kh + np * 16 + lrow;
                int bc = 2 * c + lsel;
                uint32_t kb = smb + SM_KHI + (uint32_t)(br * 256 + ((bc ^ (br & 7)) << 4));
                uint32_t bhf[4], blf[4];
                LDSM4(bhf, kb);
                LDSM4(blf, kb + (SM_KLO - SM_KHI));
                MMA(sacc[2 * np],     ah, bhf[0], bhf[2]);
                MMA(sacc[2 * np + 1], ah, bhf[1], bhf[3]);
                MMA(sacc[2 * np],     ah, blf[0], blf[2]);
                MMA(sacc[2 * np + 1], ah, blf[1], blf[3]);
                MMA(sacc[2 * np],     al, bhf[0], bhf[2]);
                MMA(sacc[2 * np + 1], al, bhf[1], bhf[3]);
            }
        }

        // ---- epilogue: mask + ex2, attn out, P split -> smem ----
        {
            const int row_lo = q0 + r0 + g, row_hi = row_lo + 8;
            const int cb = k0 + kh + qt * 2;
            const int* m_lo = mask + (size_t)row_lo * kS + cb;
            const int* m_hi = mask + (size_t)row_hi * kS + cb;
            float* a_lo = outA + ((size_t)bh * kS + row_lo) * kS + cb;
            float* a_hi = outA + ((size_t)bh * kS + row_hi) * kS + cb;
            #pragma unroll
            for (int nt = 0; nt < 4; nt++) {
                int2 m0 = *(const int2*)(m_lo + nt * 8);
                int2 m1 = *(const int2*)(m_hi + nt * 8);
                float p0 = m0.x ? ex2f(sacc[nt][0]) : 0.0f;
                float p1 = m0.y ? ex2f(sacc[nt][1]) : 0.0f;
                float p2 = m1.x ? ex2f(sacc[nt][2]) : 0.0f;
                float p3 = m1.y ? ex2f(sacc[nt][3]) : 0.0f;
                sum0 += p0 + p1;
                sum1 += p2 + p3;
                *(float2*)(a_lo + nt * 8) = make_float2(p0, p1);
                *(float2*)(a_hi + nt * 8) = make_float2(p2, p3);
                // P store: chunk = h*4 + nt, row xor with (row&7)=g, +4*qt within chunk
                uint32_t hi0, lo0, hi1, lo1;
                split2(p0, p1, hi0, lo0);
                split2(p2, p3, hi1, lo1);
                uint32_t a0 = smb + SM_PHI +
                    (uint32_t)((r0 + g) * 128 + (((h * 4 + nt) ^ g) << 4) + 4 * qt);
                uint32_t a1 = a0 + 8 * 128;
                asm volatile("st.shared.b32 [%0], %1;" :: "r"(a0), "r"(hi0));
                asm volatile("st.shared.b32 [%0], %1;" :: "r"(a0 + (SM_PLO - SM_PHI)), "r"(lo0));
                asm volatile("st.shared.b32 [%0], %1;" :: "r"(a1), "r"(hi1));
                asm volatile("st.shared.b32 [%0], %1;" :: "r"(a1 + (SM_PLO - SM_PHI)), "r"(lo1));
            }
        }
        __syncthreads();   // P complete (cross-warp exchange)

        // ---- O += P @ Vt^T : warp computes 16q x 64d (its d half) ----
        #pragma unroll
        for (int kc = 0; kc < 4; kc++) {
            uint32_t ah[4], al[4];
            {
                int ar = r0 + lrow;
                int ac = kc * 2 + lsel;
                uint32_t pa = smb + SM_PHI + (uint32_t)(ar * 128 + ((ac ^ (ar & 7)) << 4));
                LDSM4(ah, pa);
                LDSM4(al, pa + (SM_PLO - SM_PHI));
            }
            #pragma unroll
            for (int np = 0; np < 4; np++) {
                int br = h * 64 + np * 16 + lrow;
                int bc = kc * 2 + lsel;
                uint32_t vb = smb + SM_VHI + (uint32_t)(br * 128 + ((bc ^ (br & 7)) << 4));
                uint32_t bhf[4], blf[4];
                LDSM4(bhf, vb);
                LDSM4(blf, vb + (SM_VLO - SM_VHI));
                MMA(oacc[2 * np],     ah, bhf[0], bhf[2]);
                MMA(oacc[2 * np + 1], ah, bhf[1], bhf[3]);
                MMA(oacc[2 * np],     ah, blf[0], blf[2]);
                MMA(oacc[2 * np + 1], ah, blf[1], blf[3]);
                MMA(oacc[2 * np],     al, bhf[0], bhf[2]);
                MMA(oacc[2 * np + 1], al, bhf[1], bhf[3]);
            }
        }
    }

    // ---- finalize: rowsums (per key-half partials), combine, normalize ----
    __syncthreads();   // all PV reads of P done; safe to alias RSUM/INV
    sum0 += __shfl_xor_sync(0xffffffffu, sum0, 1);
    sum0 += __shfl_xor_sync(0xffffffffu, sum0, 2);
    sum1 += __shfl_xor_sync(0xffffffffu, sum1, 1);
    sum1 += __shfl_xor_sync(0xffffffffu, sum1, 2);
    float* rsum = (float*)(sm8 + SM_RSUM);
    if (qt == 0) {
        rsum[h * 64 + r0 + g]     = sum0;
        rsum[h * 64 + r0 + g + 8] = sum1;
    }
    __syncthreads();
    float* invp = (float*)(sm8 + SM_INV);
    if (tid < 64) invp[tid] = 1.0f / (rsum[tid] + rsum[64 + tid]);
    __syncthreads();

    const int row_lo = q0 + r0 + g, row_hi = row_lo + 8;
    float inv0 = invp[r0 + g], inv1 = invp[r0 + g + 8];
    float* o_lo = outO + ((size_t)bh * kS + row_lo) * kD + h * 64 + qt * 2;
    float* o_hi = outO + ((size_t)bh * kS + row_hi) * kD + h * 64 + qt * 2;
    #pragma unroll
    for (int nt = 0; nt < 8; nt++) {
        *(float2*)(o_lo + nt * 8) = make_float2(oacc[nt][0] * inv0, oacc[nt][1] * inv0);
        *(float2*)(o_hi + nt * 8) = make_float2(oacc[nt][2] * inv1, oacc[nt][3] * inv1);
    }

    // ---- tail: normalize this CTA's 64-row attn slab ----
    float* abase = outA + ((size_t)bh * kS + q0) * kS;
    #pragma unroll 4
    for (int i = 0; i < 128; i++) {
        int idx = i * kThreads + tid;
        int r = idx >> 9, c = idx & 511;
        float inv = invp[r];
        float4* p = (float4*)(abase + (size_t)r * kS) + c;
        float4 v = *p;
        v.x *= inv; v.y *= inv; v.z *= inv; v.w *= inv;
        *p = v;
    }
}

extern "C" void kernel_launch(void* const* d_in, const int* in_sizes, int n_in,
                              void* d_out, int out_size) {
    const float* Q    = (const float*)d_in[0];
    const float* K    = (const float*)d_in[1];
    const float* V    = (const float*)d_in[2];
    const int*   mask = (const int*)d_in[3];

    float* outO = (float*)d_out;
    float* outA = outO + (size_t)kBH * kS * kD;   // tuple order: (output, attn)

    cudaFuncSetAttribute(sdpa_mma_kernel, cudaFuncAttributeMaxDynamicSharedMemorySize, SM_TOTAL);

    dim3 grid(kS / kQT, kBH);
    sdpa_mma_kernel<<<grid, kThreads, SM_TOTAL>>>(Q, K, V, mask, outO, outA);
}

// round 7
// speedup vs baseline: 2.3259x; 1.5898x over previous
#include <cuda_runtime.h>
#include <cuda_fp16.h>
#include <cstdint>

// Problem: B=2, H=16, S=2048, D=128, temperature=1. Output tuple = (O, attn).
constexpr int kS = 2048;
constexpr int kD = 128;
constexpr int kBH = 32;
constexpr int kQT = 64;             // q rows per CTA
constexpr int kKT = 64;             // keys per tile
constexpr int kTiles = kS / kKT;    // 32
constexpr int kThreads = 256;       // 8 warps: (row-group 0..3) x (half 0..1)
constexpr float kScaleLog2e = 0.08838834764831845f * 1.4426950408889634f;

// smem layout (bytes) — total 112KB -> 2 CTAs/SM
constexpr int SM_QHI   = 0;        // 64x128 fp16 (256B/row, 16 chunks, swz ch^(r&7))
constexpr int SM_QLO   = 16384;
constexpr int SM_K     = 32768;    // 64x128 fp16 plain
constexpr int SM_VT    = 49152;    // 128(d) x 64(key) fp16 plain (128B/row, 8 chunks)
constexpr int SM_PHI   = 65536;    // 64x64 fp16 (128B/row, 8 chunks)
constexpr int SM_PLO   = 73728;
constexpr int SM_KSTAG = 81920;    // 64x128 fp32 raw K staging (cp.async), 32KB
constexpr int SM_TOTAL = 114688;
// post-loop aliases (P dead then):
constexpr int SM_RSUM = SM_PHI;    // 128 floats: [half][row]
constexpr int SM_INV  = SM_PLO;    // 64 floats

__device__ __forceinline__ uint32_t smem_u32(const void* p) {
    uint32_t a;
    asm("{ .reg .u64 t; cvta.to.shared.u64 t, %1; cvt.u32.u64 %0, t; }" : "=r"(a) : "l"(p));
    return a;
}
__device__ __forceinline__ float ex2f(float x) {
    float y; asm("ex2.approx.f32 %0, %1;" : "=f"(y) : "f"(x)); return y;
}

#define CP_ASYNC16(dst, src) \
    asm volatile("cp.async.cg.shared.global [%0], [%1], 16;" :: "r"(dst), "l"(src))
#define CP_COMMIT()  asm volatile("cp.async.commit_group;")
#define CP_WAIT0()   asm volatile("cp.async.wait_group 0;" ::: "memory")

#define LDSM4(r, addr) \
    asm volatile("ldmatrix.sync.aligned.m8n8.x4.shared.b16 {%0,%1,%2,%3}, [%4];" \
        : "=r"((r)[0]), "=r"((r)[1]), "=r"((r)[2]), "=r"((r)[3]) : "r"(addr))

#define MMA(c, a, b0_, b1_) \
    asm volatile("mma.sync.aligned.m16n8k16.row.col.f32.f16.f16.f32 " \
        "{%0,%1,%2,%3}, {%4,%5,%6,%7}, {%8,%9}, {%0,%1,%2,%3};" \
        : "+f"((c)[0]), "+f"((c)[1]), "+f"((c)[2]), "+f"((c)[3]) \
        : "r"((a)[0]), "r"((a)[1]), "r"((a)[2]), "r"((a)[3]), "r"(b0_), "r"(b1_))

// split two floats into fp16x2 hi + fp16x2 residual
__device__ __forceinline__ void split2h(float a, float b, uint32_t& hi, uint32_t& lo) {
    __half2 h = __floats2half2_rn(a, b);
    hi = reinterpret_cast<const uint32_t&>(h);
    float ra = a - __half2float(__low2half(h));
    float rb = b - __half2float(__high2half(h));
    __half2 l = __floats2half2_rn(ra, rb);
    lo = reinterpret_cast<const uint32_t&>(l);
}
__device__ __forceinline__ void split8h(const float* v, uint4& hi, uint4& lo) {
    uint32_t h[4], l[4];
    #pragma unroll
    for (int j = 0; j < 4; j++) split2h(v[2 * j], v[2 * j + 1], h[j], l[j]);
    hi = make_uint4(h[0], h[1], h[2], h[3]);
    lo = make_uint4(l[0], l[1], l[2], l[3]);
}
// pack 8 floats to 8 fp16 (uint4)
__device__ __forceinline__ uint4 pack8h(const float* v) {
    uint32_t h[4];
    #pragma unroll
    for (int j = 0; j < 4; j++) {
        __half2 t = __floats2half2_rn(v[2 * j], v[2 * j + 1]);
        h[j] = reinterpret_cast<const uint32_t&>(t);
    }
    return make_uint4(h[0], h[1], h[2], h[3]);
}

// issue cp.async for K tile at key offset k0 into staging (8 x 16B per thread)
__device__ __forceinline__ void cp_k(uint32_t smb, const float* Kg, int k0, int tid) {
    #pragma unroll
    for (int j = 0; j < 8; j++) {
        int idx = j * kThreads + tid;
        int row = idx >> 5, c = idx & 31;   // row 0..63, 16B chunk 0..31
        const float* src = Kg + (size_t)(k0 + row) * kD + c * 4;
        uint32_t dst = smb + SM_KSTAG + row * 512 + ((c ^ (row & 7)) << 4);
        CP_ASYNC16(dst, src);
    }
    CP_COMMIT();
}

__global__ __launch_bounds__(kThreads, 2)
void sdpa_mma_kernel(const float* __restrict__ Q, const float* __restrict__ K,
                     const float* __restrict__ V, const int* __restrict__ mask,
                     float* __restrict__ outO, float* __restrict__ outA) {
    extern __shared__ char sm8[];
    const uint32_t smb = smem_u32(sm8);
    const int tid = threadIdx.x;
    const int wid = tid >> 5, lane = tid & 31;
    const int bh = blockIdx.y;
    const int q0 = blockIdx.x * kQT;
    const int rw = wid & 3, h = wid >> 2;   // row-group / half
    const int r0 = rw * 16;                 // warp's q rows [r0, r0+16)
    const int kh = h * 32;                  // warp's key half (S phase)
    const int g  = lane >> 2;
    const int qt = lane & 3;
    const int lrow = lane & 15, lsel = lane >> 4;

    const float* Qg = Q + ((size_t)bh * kS + q0) * kD;
    const float* Kg = K + (size_t)bh * kS * kD;
    const float* Vg = V + (size_t)bh * kS * kD;

    // ---- prologue: start K0 staging; load/split Q (prescaled) ----
    cp_k(smb, Kg, 0, tid);
    #pragma unroll
    for (int it = 0; it < 4; it++) {
        int idx = it * kThreads + tid;
        int r = idx >> 4, ch = idx & 15;
        const float* qp = Qg + (size_t)r * kD + ch * 8;
        float v[8];
        #pragma unroll
        for (int j = 0; j < 8; j++) v[j] = qp[j] * kScaleLog2e;
        uint4 hi, lo; split8h(v, hi, lo);
        uint32_t off = (uint32_t)(r * 256 + ((ch ^ (r & 7)) << 4));
        *(uint4*)(sm8 + SM_QHI + off) = hi;
        *(uint4*)(sm8 + SM_QLO + off) = lo;
    }

    float oacc[8][4];
    #pragma unroll
    for (int i = 0; i < 8; i++)
        #pragma unroll
        for (int j = 0; j < 4; j++) oacc[i][j] = 0.0f;
    float sum0 = 0.0f, sum1 = 0.0f;

    for (int kt = 0; kt < kTiles; kt++) {
        const int k0 = kt * kKT;

        CP_WAIT0();
        __syncthreads();   // staging ready AND prev tile's reads of K/Vt/P done

        // ---- V tile transposed: gmem fp32 -> Vt[d][key] fp16 smem ----
        #pragma unroll
        for (int it = 0; it < 4; it++) {
            int i = it * kThreads + tid;
            int d = i & 127, kc8 = i >> 7;   // kc8 in 0..7 (8 keys per chunk)
            const float* vp = Vg + (size_t)(k0 + kc8 * 8) * kD + d;
            float v[8];
            #pragma unroll
            for (int j = 0; j < 8; j++) v[j] = vp[(size_t)j * kD];
            uint32_t off = (uint32_t)(d * 128 + ((kc8 ^ (d & 7)) << 4));
            *(uint4*)(sm8 + SM_VT + off) = pack8h(v);
        }
        // ---- K convert: staging raw fp32 -> plain fp16 smem ----
        {
            const int r = tid & 63, grp = tid >> 6;   // grp covers d = grp*32..+31
            float kv[32];
            #pragma unroll
            for (int j = 0; j < 8; j++) {
                uint32_t slot = (uint32_t)(grp * 8 + (j ^ (r & 7)));
                float4 t4 = *(const float4*)(sm8 + SM_KSTAG + r * 512 + slot * 16);
                kv[4 * j + 0] = t4.x; kv[4 * j + 1] = t4.y;
                kv[4 * j + 2] = t4.z; kv[4 * j + 3] = t4.w;
            }
            #pragma unroll
            for (int q = 0; q < 4; q++) {
                int oc = grp * 4 + q;
                uint32_t off = (uint32_t)(r * 256 + ((oc ^ (r & 7)) << 4));
                *(uint4*)(sm8 + SM_K + off) = pack8h(kv + 8 * q);
            }
        }
        __syncthreads();   // K/Vt ready; staging free

        // prefetch next K tile into staging (overlaps compute)
        if (kt + 1 < kTiles) cp_k(smb, Kg, k0 + kKT, tid);

        // hoist mask loads (L2-resident; latency covered by S phase)
        int2 m0r[4], m1r[4];
        {
            const int row_lo = q0 + r0 + g;
            const int cb = k0 + kh + qt * 2;
            const int* m_lo = mask + (size_t)row_lo * kS + cb;
            const int* m_hi = m_lo + (size_t)8 * kS;
            #pragma unroll
            for (int nt = 0; nt < 4; nt++) {
                m0r[nt] = *(const int2*)(m_lo + nt * 8);
                m1r[nt] = *(const int2*)(m_hi + nt * 8);
            }
        }

        // ---- S = Q @ K^T : warp computes 16q x 32keys (A-split fp16 2-term) ----
        float sacc[4][4];
        #pragma unroll
        for (int i = 0; i < 4; i++)
            #pragma unroll
            for (int j = 0; j < 4; j++) sacc[i][j] = 0.0f;

        #pragma unroll
        for (int c = 0; c < 8; c++) {
            uint32_t ah[4], al[4];
            {
                int ar = r0 + lrow;
                int ac = 2 * c + lsel;
                uint32_t qa = smb + SM_QHI + (uint32_t)(ar * 256 + ((ac ^ (ar & 7)) << 4));
                LDSM4(ah, qa);
                LDSM4(al, qa + (SM_QLO - SM_QHI));
            }
            #pragma unroll
            for (int np = 0; np < 2; np++) {
                int br = kh + np * 16 + lrow;
                int bc = 2 * c + lsel;
                uint32_t kb = smb + SM_K + (uint32_t)(br * 256 + ((bc ^ (br & 7)) << 4));
                uint32_t bf[4];
                LDSM4(bf, kb);
                MMA(sacc[2 * np],     ah, bf[0], bf[2]);
                MMA(sacc[2 * np + 1], ah, bf[1], bf[3]);
                MMA(sacc[2 * np],     al, bf[0], bf[2]);
                MMA(sacc[2 * np + 1], al, bf[1], bf[3]);
            }
        }

        // ---- epilogue: mask + ex2, attn out, P split fp16 -> smem ----
        {
            const int row_lo = q0 + r0 + g, row_hi = row_lo + 8;
            const int cb = k0 + kh + qt * 2;
            float* a_lo = outA + ((size_t)bh * kS + row_lo) * kS + cb;
            float* a_hi = outA + ((size_t)bh * kS + row_hi) * kS + cb;
            #pragma unroll
            for (int nt = 0; nt < 4; nt++) {
                float p0 = m0r[nt].x ? ex2f(sacc[nt][0]) : 0.0f;
                float p1 = m0r[nt].y ? ex2f(sacc[nt][1]) : 0.0f;
                float p2 = m1r[nt].x ? ex2f(sacc[nt][2]) : 0.0f;
                float p3 = m1r[nt].y ? ex2f(sacc[nt][3]) : 0.0f;
                sum0 += p0 + p1;
                sum1 += p2 + p3;
                *(float2*)(a_lo + nt * 8) = make_float2(p0, p1);
                *(float2*)(a_hi + nt * 8) = make_float2(p2, p3);
                uint32_t hi0, lo0, hi1, lo1;
                split2h(p0, p1, hi0, lo0);
                split2h(p2, p3, hi1, lo1);
                uint32_t a0 = smb + SM_PHI +
                    (uint32_t)((r0 + g) * 128 + (((h * 4 + nt) ^ g) << 4) + 4 * qt);
                uint32_t a1 = a0 + 8 * 128;
                asm volatile("st.shared.b32 [%0], %1;" :: "r"(a0), "r"(hi0));
                asm volatile("st.shared.b32 [%0], %1;" :: "r"(a0 + (SM_PLO - SM_PHI)), "r"(lo0));
                asm volatile("st.shared.b32 [%0], %1;" :: "r"(a1), "r"(hi1));
                asm volatile("st.shared.b32 [%0], %1;" :: "r"(a1 + (SM_PLO - SM_PHI)), "r"(lo1));
            }
        }
        __syncthreads();   // P complete (cross-warp exchange)

        // ---- O += P @ Vt^T : warp computes 16q x 64d (A-split fp16 2-term) ----
        #pragma unroll
        for (int kc = 0; kc < 4; kc++) {
            uint32_t ah[4], al[4];
            {
                int ar = r0 + lrow;
                int ac = kc * 2 + lsel;
                uint32_t pa = smb + SM_PHI + (uint32_t)(ar * 128 + ((ac ^ (ar & 7)) << 4));
                LDSM4(ah, pa);
                LDSM4(al, pa + (SM_PLO - SM_PHI));
            }
            #pragma unroll
            for (int np = 0; np < 4; np++) {
                int br = h * 64 + np * 16 + lrow;
                int bc = kc * 2 + lsel;
                uint32_t vb = smb + SM_VT + (uint32_t)(br * 128 + ((bc ^ (br & 7)) << 4));
                uint32_t bf[4];
                LDSM4(bf, vb);
                MMA(oacc[2 * np],     ah, bf[0], bf[2]);
                MMA(oacc[2 * np + 1], ah, bf[1], bf[3]);
                MMA(oacc[2 * np],     al, bf[0], bf[2]);
                MMA(oacc[2 * np + 1], al, bf[1], bf[3]);
            }
        }
    }

    // ---- finalize: rowsums (per key-half partials), combine, normalize ----
    __syncthreads();   // all PV reads of P done; safe to alias RSUM/INV
    sum0 += __shfl_xor_sync(0xffffffffu, sum0, 1);
    sum0 += __shfl_xor_sync(0xffffffffu, sum0, 2);
    sum1 += __shfl_xor_sync(0xffffffffu, sum1, 1);
    sum1 += __shfl_xor_sync(0xffffffffu, sum1, 2);
    float* rsum = (float*)(sm8 + SM_RSUM);
    if (qt == 0) {
        rsum[h * 64 + r0 + g]     = sum0;
        rsum[h * 64 + r0 + g + 8] = sum1;
    }
    __syncthreads();
    float* invp = (float*)(sm8 + SM_INV);
    if (tid < 64) invp[tid] = 1.0f / (rsum[tid] + rsum[64 + tid]);
    __syncthreads();

    const int row_lo = q0 + r0 + g, row_hi = row_lo + 8;
    float inv0 = invp[r0 + g], inv1 = invp[r0 + g + 8];
    float* o_lo = outO + ((size_t)bh * kS + row_lo) * kD + h * 64 + qt * 2;
    float* o_hi = outO + ((size_t)bh * kS + row_hi) * kD + h * 64 + qt * 2;
    #pragma unroll
    for (int nt = 0; nt < 8; nt++) {
        *(float2*)(o_lo + nt * 8) = make_float2(oacc[nt][0] * inv0, oacc[nt][1] * inv0);
        *(float2*)(o_hi + nt * 8) = make_float2(oacc[nt][2] * inv1, oacc[nt][3] * inv1);
    }

    // ---- tail: normalize this CTA's 64-row attn slab ----
    float* abase = outA + ((size_t)bh * kS + q0) * kS;
    #pragma unroll 4
    for (int i = 0; i < 128; i++) {
        int idx = i * kThreads + tid;
        int r = idx >> 9, c = idx & 511;
        float inv = invp[r];
        float4* p = (float4*)(abase + (size_t)r * kS) + c;
        float4 v = *p;
        v.x *= inv; v.y *= inv; v.z *= inv; v.w *= inv;
        *p = v;
    }
}

extern "C" void kernel_launch(void* const* d_in, const int* in_sizes, int n_in,
                              void* d_out, int out_size) {
    const float* Q    = (const float*)d_in[0];
    const float* K    = (const float*)d_in[1];
    const float* V    = (const float*)d_in[2];
    const int*   mask = (const int*)d_in[3];

    float* outO = (float*)d_out;
    float* outA = outO + (size_t)kBH * kS * kD;   // tuple order: (output, attn)

    cudaFuncSetAttribute(sdpa_mma_kernel, cudaFuncAttributeMaxDynamicSharedMemorySize, SM_TOTAL);

    dim3 grid(kS / kQT, kBH);
    sdpa_mma_kernel<<<grid, kThreads, SM_TOTAL>>>(Q, K, V, mask, outO, outA);
}